// round 6
// baseline (speedup 1.0000x reference)
#include <cuda_runtime.h>
#include <math.h>
#include <stdint.h>

#define Nn   32
#define Cc   192
#define Tt   256
#define Vv   25
#define Ss   3
#define MID  64
#define TV   6400          /* T*V */
#define C3   576           /* 3*C */
#define KF   1600          /* MID*Vv flattened contraction for attention */

// Scratch (static device arrays; allocation-free per harness rules)
// All intermediates store TF32-PRE-ROUNDED floats (consumers skip cvt).
__device__ float g_tok[(size_t)Nn * 3 * Ss * Tt * KF];   // token-major qkv
__device__ float g_att[(size_t)Nn * Ss * Tt * Tt];       // [ns][t][q]
__device__ float g_y[(size_t)Nn * Cc * TV];              // [n][d][t*25+v]

// ---------------------------------------------------------------------------
// helpers
// ---------------------------------------------------------------------------
__device__ __forceinline__ uint32_t f2tf32(float x) {
    uint32_t r;
    asm("cvt.rna.tf32.f32 %0, %1;" : "=r"(r) : "f"(x));
    return r;
}
__device__ __forceinline__ float rnd_tf32(float x) {
    return __uint_as_float(f2tf32(x));
}
template <bool CV>
__device__ __forceinline__ uint32_t ldf(const float* p) {
    return CV ? f2tf32(*p) : __float_as_uint(*p);
}
__device__ __forceinline__ void mma_tf32(float* d, const uint32_t* a,
                                         uint32_t b0, uint32_t b1) {
    asm volatile(
        "mma.sync.aligned.m16n8k8.row.col.f32.tf32.tf32.f32 "
        "{%0,%1,%2,%3}, {%4,%5,%6,%7}, {%8,%9}, {%0,%1,%2,%3};"
        : "+f"(d[0]), "+f"(d[1]), "+f"(d[2]), "+f"(d[3])
        : "r"(a[0]), "r"(a[1]), "r"(a[2]), "r"(a[3]), "r"(b0), "r"(b1));
}
__device__ __forceinline__ uint32_t smem_u32(const void* p) {
    return (uint32_t)__cvta_generic_to_shared(p);
}
__device__ __forceinline__ void cp16(uint32_t dst, const void* src) {
    asm volatile("cp.async.cg.shared.global [%0], [%1], 16;"
                 :: "r"(dst), "l"(src));
}
#define CP_COMMIT() asm volatile("cp.async.commit_group;")
#define CP_WAIT0()  asm volatile("cp.async.wait_group 0;" ::: "memory")

// A tiles: [m][k] XOR-16 layout: element (m,k) at m*16 + (k ^ 4*((m>>1)&3))
// B [k][n] tiles: row stride SBN, plain.  Warp tile 32m x 64n, acc[2][8][4].

template <int SBN, bool CA, bool CB>
__device__ __forceinline__ void mma_AkBn(const float* __restrict__ As,
                                         const float* __restrict__ Bs,
                                         float acc[2][8][4],
                                         int m0, int n0, int g, int ltg) {
    const int xk = 4 * ((g >> 1) & 3);
#pragma unroll
    for (int k8 = 0; k8 < 16; k8 += 8) {
        const int ka = (k8 + ltg) ^ xk;
        const int kb = (k8 + ltg + 4) ^ xk;
        uint32_t a[2][4];
#pragma unroll
        for (int mt = 0; mt < 2; mt++) {
            const float* Ar = As + (m0 + mt * 16 + g) * 16;
            a[mt][0] = ldf<CA>(Ar + ka);
            a[mt][1] = ldf<CA>(Ar + 128 + ka);   // row m+8
            a[mt][2] = ldf<CA>(Ar + kb);
            a[mt][3] = ldf<CA>(Ar + 128 + kb);
        }
        const float* B0 = Bs + (k8 + ltg) * SBN + n0 + g;
        const float* B1 = Bs + (k8 + ltg + 4) * SBN + n0 + g;
#pragma unroll
        for (int nt = 0; nt < 8; nt++) {
            const uint32_t b0 = ldf<CB>(B0 + nt * 8);
            const uint32_t b1 = ldf<CB>(B1 + nt * 8);
            mma_tf32(acc[0][nt], a[0], b0, b1);
            mma_tf32(acc[1][nt], a[1], b0, b1);
        }
    }
}

// A:[m][k]-xor16, B:[n][k]-xor16  (n-row xor factor equals g's, same xk)
template <bool CA, bool CB>
__device__ __forceinline__ void mma_AkBk(const float* __restrict__ As,
                                         const float* __restrict__ Bs,
                                         float acc[2][8][4],
                                         int m0, int n0, int g, int ltg) {
    const int xk = 4 * ((g >> 1) & 3);
#pragma unroll
    for (int k8 = 0; k8 < 16; k8 += 8) {
        const int ka = (k8 + ltg) ^ xk;
        const int kb = (k8 + ltg + 4) ^ xk;
        uint32_t a[2][4];
#pragma unroll
        for (int mt = 0; mt < 2; mt++) {
            const float* Ar = As + (m0 + mt * 16 + g) * 16;
            a[mt][0] = ldf<CA>(Ar + ka);
            a[mt][1] = ldf<CA>(Ar + 128 + ka);
            a[mt][2] = ldf<CA>(Ar + kb);
            a[mt][3] = ldf<CA>(Ar + 128 + kb);
        }
#pragma unroll
        for (int nt = 0; nt < 8; nt++) {
            const float* Br = Bs + (n0 + nt * 8 + g) * 16;
            const uint32_t b0 = ldf<CB>(Br + ka);
            const uint32_t b1 = ldf<CB>(Br + kb);
            mma_tf32(acc[0][nt], a[0], b0, b1);
            mma_tf32(acc[1][nt], a[1], b0, b1);
        }
    }
}

// ---------------------------------------------------------------------------
// Kernel 1: QKV projection. Block 64(d) x 256(p), BK=16, 1 sync/chunk.
// ---------------------------------------------------------------------------
__global__ __launch_bounds__(256, 2) void k_qkv(const float* __restrict__ x,
                                                const float* __restrict__ w_in,
                                                const float* __restrict__ b_in) {
    __shared__ __align__(16) float As[2][64 * 16];
    __shared__ __align__(16) float Bs[2][16 * 264];
    const int n  = blockIdx.z;
    const int d0 = blockIdx.y * 64;
    const int p0 = blockIdx.x * 256;
    const int tid = threadIdx.x, warp = tid >> 5, lane = tid & 31;
    const int wm = warp >> 2, wn = warp & 3;
    const int g = lane >> 2, ltg = lane & 3;

    const float* xn = x + (size_t)n * Cc * TV;

    const int ar = tid >> 2, au = tid & 3;
    const int axc = 4 * (au ^ ((ar >> 1) & 3));
    const int br = tid >> 4, bc4 = (tid & 15) * 4;

    auto stage = [&](int buf, int k0) {
        cp16(smem_u32(&As[buf][ar * 16 + axc]),
             &w_in[(size_t)(d0 + ar) * Cc + k0 + au * 4]);
        const float* src = &xn[(size_t)(k0 + br) * TV + p0 + bc4];
        float* dst = &Bs[buf][br * 264 + bc4];
#pragma unroll
        for (int u = 0; u < 4; u++)
            cp16(smem_u32(dst + u * 64), src + u * 64);
        CP_COMMIT();
    };

    float acc[2][8][4] = {};
    stage(0, 0);
    const int NC = Cc / 16;
#pragma unroll 1
    for (int c = 0; c < NC; c++) {
        CP_WAIT0();
        __syncthreads();
        if (c + 1 < NC) stage((c + 1) & 1, (c + 1) * 16);
        mma_AkBn<264, true, true>(As[c & 1], Bs[c & 1], acc,
                                  wm * 32, wn * 64, g, ltg);
    }

    // epilogue: scatter to token-major layout, pre-rounded to tf32
    const int part = d0 / Cc;
    const int s = (d0 % Cc) / MID;
    float* base = g_tok + (((size_t)(n * 3 + part) * Ss + s) * Tt) * KF;
#pragma unroll
    for (int mt = 0; mt < 2; mt++)
#pragma unroll
        for (int half = 0; half < 2; half++) {
            const int cch = wm * 32 + mt * 16 + g + half * 8;
            const float bias = b_in[d0 + cch];
#pragma unroll
            for (int nt = 0; nt < 8; nt++)
#pragma unroll
                for (int e = 0; e < 2; e++) {
                    const int p = p0 + wn * 64 + nt * 8 + ltg * 2 + e;
                    const int t = p / 25, v = p - t * 25;
                    base[(size_t)t * KF + cch * 25 + v] =
                        rnd_tf32(acc[mt][nt][half * 2 + e] + bias);
                }
        }
}

// ---------------------------------------------------------------------------
// Kernel 2: att = tanh(Q K^T / 1600). Block 64(t) x 256(q), K=1600, BK=16.
// Operands pre-rounded -> cvt-free hot loop.
// ---------------------------------------------------------------------------
__global__ __launch_bounds__(256, 2) void k_att() {
    __shared__ __align__(16) float As[2][64 * 16];
    __shared__ __align__(16) float Bs[2][256 * 16];
    const int ns = blockIdx.z;
    const int n = ns / 3, s = ns - 3 * n;
    const int t0 = blockIdx.y * 64;
    const int tid = threadIdx.x, warp = tid >> 5, lane = tid & 31;
    const int wm = warp >> 2, wn = warp & 3;
    const int g = lane >> 2, ltg = lane & 3;

    const float* Qb = g_tok + (((size_t)(n * 3 + 0) * Ss + s) * Tt) * KF;
    const float* Kb = g_tok + (((size_t)(n * 3 + 1) * Ss + s) * Tt) * KF;

    const int ar = tid >> 2, au = tid & 3;
    const int axc = 4 * (au ^ ((ar >> 1) & 3));

    auto stage = [&](int buf, int k0) {
        cp16(smem_u32(&As[buf][ar * 16 + axc]),
             &Qb[(size_t)(t0 + ar) * KF + k0 + au * 4]);
#pragma unroll
        for (int i = 0; i < 4; i++) {
            const int q = ar + 64 * i;
            cp16(smem_u32(&Bs[buf][q * 16 + axc]),
                 &Kb[(size_t)q * KF + k0 + au * 4]);
        }
        CP_COMMIT();
    };

    float acc[2][8][4] = {};
    stage(0, 0);
    const int NC = KF / 16;
#pragma unroll 1
    for (int c = 0; c < NC; c++) {
        CP_WAIT0();
        __syncthreads();
        if (c + 1 < NC) stage((c + 1) & 1, (c + 1) * 16);
        mma_AkBk<false, false>(As[c & 1], Bs[c & 1], acc,
                               wm * 32, wn * 64, g, ltg);
    }

    const float scale = 1.0f / (float)KF;
    float* arow = g_att + (size_t)ns * Tt * Tt;
#pragma unroll
    for (int mt = 0; mt < 2; mt++)
#pragma unroll
        for (int half = 0; half < 2; half++) {
            const int t = t0 + wm * 32 + mt * 16 + g + half * 8;
#pragma unroll
            for (int nt = 0; nt < 8; nt++) {
                const int q = wn * 64 + nt * 8 + ltg * 2;
                float2 o;
                o.x = rnd_tf32(tanhf(acc[mt][nt][half * 2 + 0] * scale));
                o.y = rnd_tf32(tanhf(acc[mt][nt][half * 2 + 1] * scale));
                *(float2*)&arow[(size_t)t * Tt + q] = o;
            }
        }
}

// ---------------------------------------------------------------------------
// Kernel 3: y = att @ V_t. Block 256(t, 8 warps) x 64(j), K=256, cvt-free.
// ---------------------------------------------------------------------------
__global__ __launch_bounds__(256, 2) void k_y() {
    __shared__ __align__(16) float As[2][256 * 16];
    __shared__ __align__(16) float Bs[2][16 * 72];
    const int ns = blockIdx.z;
    const int n = ns / 3, s = ns - 3 * n;
    const int j0 = blockIdx.x * 64;
    const int tid = threadIdx.x, warp = tid >> 5, lane = tid & 31;
    const int g = lane >> 2, ltg = lane & 3;

    const float* att = g_att + (size_t)ns * Tt * Tt;
    const float* Vb  = g_tok + (((size_t)(n * 3 + 2) * Ss + s) * Tt) * KF;

    const int ar = tid >> 2, au = tid & 3;
    const int axc = 4 * (au ^ ((ar >> 1) & 3));
    const int br = tid >> 4, bc4 = (tid & 15) * 4;

    auto stage = [&](int buf, int k0) {
#pragma unroll
        for (int i = 0; i < 4; i++) {
            const int t = ar + 64 * i;
            cp16(smem_u32(&As[buf][t * 16 + axc]),
                 &att[(size_t)t * Tt + k0 + au * 4]);
        }
        cp16(smem_u32(&Bs[buf][br * 72 + bc4]),
             &Vb[(size_t)(k0 + br) * KF + j0 + bc4]);
        CP_COMMIT();
    };

    float acc[2][8][4] = {};
    stage(0, 0);
    const int NC = Tt / 16;
#pragma unroll 1
    for (int c = 0; c < NC; c++) {
        CP_WAIT0();
        __syncthreads();
        if (c + 1 < NC) stage((c + 1) & 1, (c + 1) * 16);
        mma_AkBn<72, false, false>(As[c & 1], Bs[c & 1], acc,
                                   warp * 32, 0, g, ltg);
    }

    float* yb = g_y + (size_t)n * Cc * TV + (size_t)(s * MID) * TV;
#pragma unroll
    for (int mt = 0; mt < 2; mt++)
#pragma unroll
        for (int half = 0; half < 2; half++) {
            const int t = warp * 32 + mt * 16 + g + half * 8;
#pragma unroll
            for (int nt = 0; nt < 8; nt++)
#pragma unroll
                for (int e = 0; e < 2; e++) {
                    const int j = j0 + nt * 8 + ltg * 2 + e;
                    const int cch = j / 25, v = j - cch * 25;
                    yb[(size_t)cch * TV + t * 25 + v] =
                        rnd_tf32(acc[mt][nt][half * 2 + e]);
                }
        }
}

// ---------------------------------------------------------------------------
// Kernel 4: FF + BN + residual + LeakyReLU. Block 64(d) x 256(p), BK=16.
// B operand (g_y) pre-rounded; A (w_ff) cvt at fragment load.
// ---------------------------------------------------------------------------
__global__ __launch_bounds__(256, 2) void k_ff(const float* __restrict__ x,
                                               const float* __restrict__ w_ff,
                                               const float* __restrict__ b_ff,
                                               const float* __restrict__ gamma,
                                               const float* __restrict__ beta,
                                               const float* __restrict__ mean,
                                               const float* __restrict__ var,
                                               float* __restrict__ out) {
    __shared__ __align__(16) float As[2][64 * 16];
    __shared__ __align__(16) float Bs[2][16 * 264];
    const int n  = blockIdx.z;
    const int d0 = blockIdx.y * 64;
    const int p0 = blockIdx.x * 256;
    const int tid = threadIdx.x, warp = tid >> 5, lane = tid & 31;
    const int wm = warp >> 2, wn = warp & 3;
    const int g = lane >> 2, ltg = lane & 3;

    const float* yn = g_y + (size_t)n * Cc * TV;

    const int ar = tid >> 2, au = tid & 3;
    const int axc = 4 * (au ^ ((ar >> 1) & 3));
    const int br = tid >> 4, bc4 = (tid & 15) * 4;

    auto stage = [&](int buf, int k0) {
        cp16(smem_u32(&As[buf][ar * 16 + axc]),
             &w_ff[(size_t)(d0 + ar) * Cc + k0 + au * 4]);
        const float* src = &yn[(size_t)(k0 + br) * TV + p0 + bc4];
        float* dst = &Bs[buf][br * 264 + bc4];
#pragma unroll
        for (int u = 0; u < 4; u++)
            cp16(smem_u32(dst + u * 64), src + u * 64);
        CP_COMMIT();
    };

    float acc[2][8][4] = {};
    stage(0, 0);
    const int NC = Cc / 16;
#pragma unroll 1
    for (int c = 0; c < NC; c++) {
        CP_WAIT0();
        __syncthreads();
        if (c + 1 < NC) stage((c + 1) & 1, (c + 1) * 16);
        mma_AkBn<264, true, false>(As[c & 1], Bs[c & 1], acc,
                                   wm * 32, wn * 64, g, ltg);
    }

    const float* xn = x + (size_t)n * Cc * TV;
    float* on = out + (size_t)n * Cc * TV;
#pragma unroll
    for (int mt = 0; mt < 2; mt++)
#pragma unroll
        for (int half = 0; half < 2; half++) {
            const int d = d0 + wm * 32 + mt * 16 + g + half * 8;
            const float inv = gamma[d] * rsqrtf(var[d] + 1e-5f);
            const float add = (b_ff[d] - mean[d]) * inv + beta[d];
#pragma unroll
            for (int nt = 0; nt < 8; nt++) {
                const int p = p0 + wn * 64 + nt * 8 + ltg * 2;
                const size_t off = (size_t)d * TV + p;
                float2 xv = *(const float2*)&xn[off];
                float z0 = xv.x + acc[mt][nt][half * 2 + 0] * inv + add;
                float z1 = xv.y + acc[mt][nt][half * 2 + 1] * inv + add;
                float2 o;
                o.x = z0 >= 0.f ? z0 : 0.1f * z0;
                o.y = z1 >= 0.f ? z1 : 0.1f * z1;
                *(float2*)&on[off] = o;
            }
        }
}

// ---------------------------------------------------------------------------
extern "C" void kernel_launch(void* const* d_in, const int* in_sizes, int n_in,
                              void* d_out, int out_size) {
    (void)in_sizes; (void)n_in; (void)out_size;
    const float* x     = (const float*)d_in[0];
    const float* w_in  = (const float*)d_in[1];
    const float* b_in  = (const float*)d_in[2];
    const float* w_ff  = (const float*)d_in[3];
    const float* b_ff  = (const float*)d_in[4];
    const float* gamma = (const float*)d_in[5];
    const float* beta  = (const float*)d_in[6];
    const float* mean  = (const float*)d_in[7];
    const float* var   = (const float*)d_in[8];
    float* out = (float*)d_out;

    k_qkv<<<dim3(TV / 256, C3 / 64, Nn), 256>>>(x, w_in, b_in);
    k_att<<<dim3(1, Tt / 64, Nn * Ss), 256>>>();
    k_y  <<<dim3(KF / 64, 1, Nn * Ss), 256>>>();
    k_ff <<<dim3(TV / 256, Cc / 64, Nn), 256>>>(x, w_ff, b_ff, gamma, beta,
                                                mean, var, out);
}